// round 11
// baseline (speedup 1.0000x reference)
#include <cuda_runtime.h>
#include <cuda_bf16.h>
#include <cstdint>

#define NN 20000
#define NE 320000
#define CC 64
#define PL (NN*CC)

typedef unsigned long long ull;

// Scratch (allocation-free rule: __device__ globals)
__device__ __align__(16) float g_h[NN*CC];        // 5.1 MB
__device__ __align__(16) float g_agg[9*PL];       // 46 MB (atomic target, planar)
__device__ __align__(16) uint4 g_wfrag[264*32];   // 135 KB packed B fragments (MLP + down)
__device__ int g_cnt[NN];
__device__ int g_off[NN+1];
__device__ int g_cur[NN];
__device__ int g_order[NE];

// silu via hardware tanh: x*sigmoid(x) = 0.5x*tanh(0.5x) + 0.5x
__device__ __forceinline__ float silu(float x) {
    float hx = 0.5f * x;
    float t;
    asm("tanh.approx.f32 %0, %1;" : "=f"(t) : "f"(hx));
    return fmaf(hx, t, hx);
}
__device__ __forceinline__ void red2(float* p, float a, float b) {
    asm volatile("red.global.add.v2.f32 [%0], {%1,%2};" :: "l"(p), "f"(a), "f"(b) : "memory");
}

// pack (x0 -> low half, x1 -> high half) as bf16x2; return hi-word, write lo(residual)-word
__device__ __forceinline__ uint32_t split_pair(float x0, float x1, uint32_t& lw) {
    uint32_t hw;
    asm("cvt.rn.bf16x2.f32 %0, %1, %2;" : "=r"(hw) : "f"(x1), "f"(x0));
    float h0 = __uint_as_float(hw << 16);
    float h1 = __uint_as_float(hw & 0xffff0000u);
    asm("cvt.rn.bf16x2.f32 %0, %1, %2;" : "=r"(lw) : "f"(x1 - h1), "f"(x0 - h0));
    return hw;
}

__device__ __forceinline__ void mma16816(float c[4],
    uint32_t a0, uint32_t a1, uint32_t a2, uint32_t a3, uint32_t b0, uint32_t b1)
{
    asm volatile("mma.sync.aligned.m16n8k16.row.col.f32.bf16.bf16.f32 "
        "{%0,%1,%2,%3},{%4,%5,%6,%7},{%8,%9},{%0,%1,%2,%3};"
        : "+f"(c[0]), "+f"(c[1]), "+f"(c[2]), "+f"(c[3])
        : "r"(a0), "r"(a1), "r"(a2), "r"(a3), "r"(b0), "r"(b1));
}

// ---------------------------------------------------------------- histinit: hist + pack B frags + up-proj
// blocks [0,1250): histogram ; [1250,1514): fragment tiles ; [1514, 1514+5000): up projection
__global__ __launch_bounds__(256) void histinit_kernel(
    const int* __restrict__ receivers,
    const float* __restrict__ nf, const float* __restrict__ wup,
    const float* __restrict__ w1, const float* __restrict__ w2,
    const float* __restrict__ w3, const float* __restrict__ w4,
    const float* __restrict__ wd0, const float* __restrict__ wd1,
    const float* __restrict__ wd2)
{
    if (blockIdx.x < 1250) {
        int e = blockIdx.x * 256 + threadIdx.x;
        atomicAdd(&g_cnt[receivers[e]], 1);
        return;
    }
    if (blockIdx.x < 1514) {
        if (threadIdx.x < 32) {
            const int tile = blockIdx.x - 1250;
            const int lane = threadIdx.x;
            const int g = lane >> 2, tig = lane & 3;
            const float* W; int K, Nc, kt, nt; float sc;
            if (tile < 8)        { W = w1;  K = 8;  Nc = 64;  kt = 0;      nt = tile;    sc = 0.35355339059f; }
            else if (tile < 40)  { int t = tile-8;   W = w2;  K = 64; Nc = 64;  kt = t >> 3; nt = t & 7;  sc = 0.125f; }
            else if (tile < 72)  { int t = tile-40;  W = w3;  K = 64; Nc = 64;  kt = t >> 3; nt = t & 7;  sc = 0.125f; }
            else if (tile < 168) { int t = tile-72;  W = w4;  K = 64; Nc = 192; kt = t / 24; nt = t % 24; sc = 0.001953125f; }
            else if (tile < 200) { int t = tile-168; W = wd0; K = 64; Nc = 64;  kt = t >> 3; nt = t & 7;  sc = 0.0625f; }
            else if (tile < 232) { int t = tile-200; W = wd1; K = 64; Nc = 64;  kt = t >> 3; nt = t & 7;  sc = 0.0625f; }
            else                 { int t = tile-232; W = wd2; K = 64; Nc = 64;  kt = t >> 3; nt = t & 7;  sc = 0.0625f; }
            const int n = nt*8 + g;
            const int k0 = kt*16 + 2*tig;
            float x00 = (k0   < K) ? W[(k0  )*Nc + n]*sc : 0.f;
            float x01 = (k0+1 < K) ? W[(k0+1)*Nc + n]*sc : 0.f;
            float x10 = (k0+8 < K) ? W[(k0+8)*Nc + n]*sc : 0.f;
            float x11 = (k0+9 < K) ? W[(k0+9)*Nc + n]*sc : 0.f;
            uint32_t l0, l1;
            uint32_t h0 = split_pair(x00, x01, l0);
            uint32_t h1 = split_pair(x10, x11, l1);
            g_wfrag[tile*32 + lane] = make_uint4(h0, h1, l0, l1);
        }
        return;
    }
    // ---- up projection ----
    __shared__ float ws[CC*CC];
    __shared__ float rows[4*CC];
    const int ub = blockIdx.x - 1514;
    for (int i = threadIdx.x; i < CC*CC; i += 256) ws[i] = wup[i];
    int base = ub * 4 * CC;
    rows[threadIdx.x] = nf[base + threadIdx.x];
    __syncthreads();
    int r = threadIdx.x >> 6;
    int c = threadIdx.x & 63;
    float acc = 0.f;
    #pragma unroll
    for (int i = 0; i < CC; i++) acc = fmaf(rows[r*CC + i], ws[i*CC + c], acc);
    g_h[base + threadIdx.x] = acc * 0.125f;
}

// ---------------------------------------------------------------- scan (also re-zeroes g_cnt for next replay)
__global__ void scan_kernel() {
    __shared__ int part[1024];
    const int t = threadIdx.x;
    const int base = t * 20;
    int sum = 0;
    if (t < 1000) {
        #pragma unroll
        for (int k = 0; k < 20; k++) sum += g_cnt[base + k];
    }
    part[t] = sum;
    __syncthreads();
    #pragma unroll
    for (int off = 1; off < 1024; off <<= 1) {
        int v = (t >= off) ? part[t - off] : 0;
        __syncthreads();
        part[t] += v;
        __syncthreads();
    }
    if (t < 1000) {
        int run = part[t] - sum;
        #pragma unroll
        for (int k = 0; k < 20; k++) {
            g_off[base + k] = run;
            g_cur[base + k] = run;
            run += g_cnt[base + k];
            g_cnt[base + k] = 0;   // re-zero for next graph replay
        }
    }
    if (t == 0) g_off[NN] = NE;
}

__global__ void order_kernel(const int* __restrict__ receivers) {
    int e = blockIdx.x * blockDim.x + threadIdx.x;
    if (e < NE) {
        int pos = atomicAdd(&g_cur[receivers[e]], 1);
        g_order[pos] = e;
    }
}

// ---------------------------------------------------------------- shared mma helpers
__device__ __forceinline__ void layerK64(int tbase, int lane, float C[8][4],
                                         const uint32_t Ah[4][4], const uint32_t Al[4][4])
{
    #pragma unroll
    for (int nt = 0; nt < 8; nt++) {
        C[nt][0] = C[nt][1] = C[nt][2] = C[nt][3] = 0.f;
        #pragma unroll
        for (int kt = 0; kt < 4; kt++) {
            uint4 wf = g_wfrag[(tbase + kt*8 + nt)*32 + lane];
            mma16816(C[nt], Ah[kt][0], Ah[kt][1], Ah[kt][2], Ah[kt][3], wf.x, wf.y);
            mma16816(C[nt], Ah[kt][0], Ah[kt][1], Ah[kt][2], Ah[kt][3], wf.z, wf.w);
            mma16816(C[nt], Al[kt][0], Al[kt][1], Al[kt][2], Al[kt][3], wf.x, wf.y);
        }
    }
}

__device__ __forceinline__ void transition(const float C[8][4], uint32_t Ah[4][4], uint32_t Al[4][4])
{
    #pragma unroll
    for (int kt = 0; kt < 4; kt++) {
        const float* ca = C[2*kt];
        const float* cb = C[2*kt+1];
        Ah[kt][0] = split_pair(silu(ca[0]), silu(ca[1]), Al[kt][0]);
        Ah[kt][1] = split_pair(silu(ca[2]), silu(ca[3]), Al[kt][1]);
        Ah[kt][2] = split_pair(silu(cb[0]), silu(cb[1]), Al[kt][2]);
        Ah[kt][3] = split_pair(silu(cb[2]), silu(cb[3]), Al[kt][3]);
    }
}

// per-warp chunk tile: 16 rows x 64 cols, stride 66
#define TROW 66
#define TILE_F (16*TROW)                       // 1056 floats
#define EY_OFF (4*TILE_F)                      // y after 4 warp tiles
#define ESMEM_F (4*TILE_F + 4*128 + 4*16)      // 4800 floats = 19200 B

// ---------------------------------------------------------------- edgeM: MLP (mma) + fused chunked segmented scatter
__global__ __launch_bounds__(128) void edgeM_kernel(
    const float* __restrict__ vectors, const float* __restrict__ radial,
    const int* __restrict__ senders, const int* __restrict__ receivers)
{
    extern __shared__ float esm[];
    const int wid = threadIdx.x >> 5;
    const int lane = threadIdx.x & 31;
    float* tw = esm + wid*TILE_F;
    float* yw = esm + EY_OFF + wid*128;
    int*   rcw = (int*)(esm + EY_OFF + 4*128) + wid*16;

    const int wt = blockIdx.x*4 + wid;
    const int g = lane >> 2, tig = lane & 3;
    const int base = wt*16;
    const int p0 = base + g, p1 = p0 + 8;
    const int e0 = g_order[p0], e1 = g_order[p1];

    // ---- SH + receiver ids -> smem (early, so reduction can run per chunk) ----
    if (lane < 16) {
        const int e = g_order[base + lane];
        float vx = vectors[e*3], vy = vectors[e*3+1], vz = vectors[e*3+2];
        float inv = rsqrtf(vx*vx + vy*vy + vz*vz);
        float ux = vx*inv, uy = vy*inv, uz = vz*inv;
        const float SQ3 = 1.7320508075688772f, S15 = 3.872983346207417f;
        const float HS5 = 1.118033988749895f;
        float* yr = yw + lane*8;
        yr[0] = SQ3*ux; yr[1] = SQ3*uy; yr[2] = SQ3*uz;
        yr[3] = S15*ux*uy; yr[4] = S15*uy*uz; yr[5] = HS5*(3.f*uz*uz - 1.f);
        yr[6] = S15*ux*uz; yr[7] = 0.5f*S15*(ux*ux - uy*uy);
        rcw[lane] = receivers[e];
    }

    uint32_t Ah[4][4], Al[4][4];
    {
        float2 r0 = *(const float2*)(radial + (size_t)e0*8 + 2*tig);
        float2 r1 = *(const float2*)(radial + (size_t)e1*8 + 2*tig);
        Ah[0][0] = split_pair(r0.x, r0.y, Al[0][0]);
        Ah[0][1] = split_pair(r1.x, r1.y, Al[0][1]);
        Ah[0][2] = 0; Ah[0][3] = 0; Al[0][2] = 0; Al[0][3] = 0;
    }

    float C[8][4];
    // ---- L1 ----
    #pragma unroll
    for (int nt = 0; nt < 8; nt++) {
        C[nt][0] = C[nt][1] = C[nt][2] = C[nt][3] = 0.f;
        uint4 wf = g_wfrag[nt*32 + lane];
        mma16816(C[nt], Ah[0][0], Ah[0][1], Ah[0][2], Ah[0][3], wf.x, wf.y);
        mma16816(C[nt], Ah[0][0], Ah[0][1], Ah[0][2], Ah[0][3], wf.z, wf.w);
        mma16816(C[nt], Al[0][0], Al[0][1], Al[0][2], Al[0][3], wf.x, wf.y);
    }
    transition(C, Ah, Al);
    layerK64(8, lane, C, Ah, Al);    // L2
    transition(C, Ah, Al);
    layerK64(40, lane, C, Ah, Al);   // L3
    transition(C, Ah, Al);

    const int snd0 = senders[e0], snd1 = senders[e1];
    const float* h0r = g_h + (size_t)snd0*64;
    const float* h1r = g_h + (size_t)snd1*64;
    const int c0 = 2*lane;

    // ---- L4 chunk-by-chunk: compute D, stage 16x64 tile, reduce immediately ----
    #pragma unroll
    for (int p = 0; p < 3; p++) {
        float D[8][4];
        #pragma unroll
        for (int ntl = 0; ntl < 8; ntl++) {
            D[ntl][0] = D[ntl][1] = D[ntl][2] = D[ntl][3] = 0.f;
            #pragma unroll
            for (int kt = 0; kt < 4; kt++) {
                uint4 wf = g_wfrag[(72 + kt*24 + p*8 + ntl)*32 + lane];
                mma16816(D[ntl], Ah[kt][0], Ah[kt][1], Ah[kt][2], Ah[kt][3], wf.x, wf.y);
                mma16816(D[ntl], Ah[kt][0], Ah[kt][1], Ah[kt][2], Ah[kt][3], wf.z, wf.w);
                mma16816(D[ntl], Al[kt][0], Al[kt][1], Al[kt][2], Al[kt][3], wf.x, wf.y);
            }
        }
        #pragma unroll
        for (int ntl = 0; ntl < 8; ntl++) {
            int col = 8*ntl + 2*tig;
            float2 h0 = *(const float2*)(h0r + col);
            float2 h1 = *(const float2*)(h1r + col);
            *(float2*)(tw + g*TROW + col)     = make_float2(D[ntl][0]*h0.x, D[ntl][1]*h0.y);
            *(float2*)(tw + (g+8)*TROW + col) = make_float2(D[ntl][2]*h1.x, D[ntl][3]*h1.y);
        }
        __syncwarp();

        // segmented reduction for this chunk's planes
        const int np = (p == 0) ? 1 : ((p == 1) ? 3 : 5);
        const int pb = (p == 0) ? 0 : ((p == 1) ? 1 : 4);
        const int yb = 3*(p - 1);   // valid for p>=1
        float acc[5][2];
        #pragma unroll
        for (int m = 0; m < 5; m++) { acc[m][0] = 0.f; acc[m][1] = 0.f; }
        int prev = rcw[0];

        #pragma unroll 1
        for (int r = 0; r < 16; r++) {
            int rc = rcw[r];
            if (rc != prev) {
                float* ab = g_agg + (size_t)prev*64 + c0;
                #pragma unroll
                for (int m = 0; m < np; m++) {
                    red2(ab + (size_t)(pb+m)*PL, acc[m][0], acc[m][1]);
                    acc[m][0] = 0.f; acc[m][1] = 0.f;
                }
                prev = rc;
            }
            float2 t = *(const float2*)(tw + r*TROW + c0);
            if (p == 0) {
                acc[0][0] += t.x; acc[0][1] += t.y;
            } else {
                const float* yr = yw + r*8 + yb;
                #pragma unroll
                for (int m = 0; m < np; m++) {
                    float ym = yr[m];
                    acc[m][0] = fmaf(t.x, ym, acc[m][0]);
                    acc[m][1] = fmaf(t.y, ym, acc[m][1]);
                }
            }
        }
        {
            float* ab = g_agg + (size_t)prev*64 + c0;
            #pragma unroll
            for (int m = 0; m < np; m++)
                red2(ab + (size_t)(pb+m)*PL, acc[m][0], acc[m][1]);
        }
        __syncwarp();
    }
}

// ---------------------------------------------------------------- down projection via mma
#define NJOBS (9*1250)
__global__ __launch_bounds__(128) void downM_kernel(float* __restrict__ out)
{
    const int job = blockIdx.x*4 + (threadIdx.x >> 5);
    if (job >= NJOBS) return;
    const int lane = threadIdx.x & 31;
    const int g = lane >> 2, tig = lane & 3;
    const int plane = job / 1250;
    const int n0 = (job - plane*1250) * 16;

    const float* ar = g_agg + (size_t)plane*PL;
    uint32_t Ah[4][4], Al[4][4];
    #pragma unroll
    for (int kt = 0; kt < 4; kt++) {
        const int c0 = kt*16 + 2*tig;
        const float* r0p = ar + (size_t)(n0+g)*64 + c0;
        const float* r1p = ar + (size_t)(n0+g+8)*64 + c0;
        float2 a00 = *(const float2*)(r0p);
        float2 a01 = *(const float2*)(r0p + 8);
        float2 a10 = *(const float2*)(r1p);
        float2 a11 = *(const float2*)(r1p + 8);
        Ah[kt][0] = split_pair(a00.x, a00.y, Al[kt][0]);
        Ah[kt][1] = split_pair(a10.x, a10.y, Al[kt][1]);
        Ah[kt][2] = split_pair(a01.x, a01.y, Al[kt][2]);
        Ah[kt][3] = split_pair(a11.x, a11.y, Al[kt][3]);
    }

    const int tbase = 168 + (plane == 0 ? 0 : (plane < 4 ? 32 : 64));
    float C[8][4];
    layerK64(tbase, lane, C, Ah, Al);

    float* ob0 = out + (size_t)(n0+g)*576;
    float* ob1 = out + (size_t)(n0+g+8)*576;
    if (plane == 0) {
        #pragma unroll
        for (int nt = 0; nt < 8; nt++) {
            int d = 8*nt + 2*tig;
            *(float2*)(ob0 + d) = make_float2(C[nt][0], C[nt][1]);
            *(float2*)(ob1 + d) = make_float2(C[nt][2], C[nt][3]);
        }
    } else if (plane < 4) {
        float* b0 = ob0 + 64 + (plane - 1);
        float* b1 = ob1 + 64 + (plane - 1);
        #pragma unroll
        for (int nt = 0; nt < 8; nt++) {
            int d = 8*nt + 2*tig;
            b0[3*d] = C[nt][0]; b0[3*(d+1)] = C[nt][1];
            b1[3*d] = C[nt][2]; b1[3*(d+1)] = C[nt][3];
        }
    } else {
        float* b0 = ob0 + 256 + (plane - 4);
        float* b1 = ob1 + 256 + (plane - 4);
        #pragma unroll
        for (int nt = 0; nt < 8; nt++) {
            int d = 8*nt + 2*tig;
            b0[5*d] = C[nt][0]; b0[5*(d+1)] = C[nt][1];
            b1[5*d] = C[nt][2]; b1[5*(d+1)] = C[nt][3];
        }
    }
}

// ---------------------------------------------------------------- launch
extern "C" void kernel_launch(void* const* d_in, const int* in_sizes, int n_in,
                              void* d_out, int out_size)
{
    const float* vectors    = (const float*)d_in[0];
    const float* node_feats = (const float*)d_in[1];
    const float* radial     = (const float*)d_in[2];
    const int*   senders    = (const int*)  d_in[3];
    const int*   receivers  = (const int*)  d_in[4];
    const float* w_up       = (const float*)d_in[5];
    const float* mlp_w1     = (const float*)d_in[6];
    const float* mlp_w2     = (const float*)d_in[7];
    const float* mlp_w3     = (const float*)d_in[8];
    const float* mlp_w4     = (const float*)d_in[9];
    const float* w_down0    = (const float*)d_in[10];
    const float* w_down1    = (const float*)d_in[11];
    const float* w_down2    = (const float*)d_in[12];
    float* out = (float*)d_out;

    const int E_SMEM = ESMEM_F * 4;   // 19200 B
    cudaFuncSetAttribute(edgeM_kernel, cudaFuncAttributeMaxDynamicSharedMemorySize, E_SMEM);

    void* aggp = nullptr;
    cudaGetSymbolAddress(&aggp, g_agg);
    cudaMemsetAsync(aggp, 0, (size_t)9 * PL * sizeof(float));                     // launch 1

    histinit_kernel<<<1514 + NN/4, 256>>>(receivers, node_feats, w_up,            // launch 2
                                          mlp_w1, mlp_w2, mlp_w3, mlp_w4,
                                          w_down0, w_down1, w_down2);
    scan_kernel<<<1, 1024>>>();                                                   // launch 3
    order_kernel<<<(NE + 255)/256, 256>>>(receivers);                             // launch 4
    edgeM_kernel<<<NE/(16*4), 128, E_SMEM>>>(vectors, radial, senders, receivers);// launch 5  <- ncu slot
    downM_kernel<<<(NJOBS + 3)/4, 128>>>(out);                                    // launch 6
}

// round 12
// speedup vs baseline: 1.0605x; 1.0605x over previous
#include <cuda_runtime.h>
#include <cuda_bf16.h>
#include <cstdint>

#define NN 20000
#define NE 320000
#define CC 64
#define PL (NN*CC)

typedef unsigned long long ull;

// Scratch (allocation-free rule: __device__ globals)
__device__ __align__(16) float g_h[NN*CC];        // 5.1 MB
__device__ __align__(16) float g_agg[9*PL];       // 46 MB (atomic target, planar)
__device__ __align__(16) uint4 g_wfrag[264*32];   // 135 KB packed B fragments (MLP + down)
__device__ int g_cnt[NN];
__device__ int g_off[NN+1];
__device__ int g_cur[NN];
__device__ int g_order[NE];

// silu via hardware tanh: x*sigmoid(x) = 0.5x*tanh(0.5x) + 0.5x
__device__ __forceinline__ float silu(float x) {
    float hx = 0.5f * x;
    float t;
    asm("tanh.approx.f32 %0, %1;" : "=f"(t) : "f"(hx));
    return fmaf(hx, t, hx);
}
__device__ __forceinline__ void red2(float* p, float a, float b) {
    asm volatile("red.global.add.v2.f32 [%0], {%1,%2};" :: "l"(p), "f"(a), "f"(b) : "memory");
}

// pack (x0 -> low half, x1 -> high half) as bf16x2; return hi-word, write lo(residual)-word
__device__ __forceinline__ uint32_t split_pair(float x0, float x1, uint32_t& lw) {
    uint32_t hw;
    asm("cvt.rn.bf16x2.f32 %0, %1, %2;" : "=r"(hw) : "f"(x1), "f"(x0));
    float h0 = __uint_as_float(hw << 16);
    float h1 = __uint_as_float(hw & 0xffff0000u);
    asm("cvt.rn.bf16x2.f32 %0, %1, %2;" : "=r"(lw) : "f"(x1 - h1), "f"(x0 - h0));
    return hw;
}

__device__ __forceinline__ void mma16816(float c[4],
    uint32_t a0, uint32_t a1, uint32_t a2, uint32_t a3, uint32_t b0, uint32_t b1)
{
    asm volatile("mma.sync.aligned.m16n8k16.row.col.f32.bf16.bf16.f32 "
        "{%0,%1,%2,%3},{%4,%5,%6,%7},{%8,%9},{%0,%1,%2,%3};"
        : "+f"(c[0]), "+f"(c[1]), "+f"(c[2]), "+f"(c[3])
        : "r"(a0), "r"(a1), "r"(a2), "r"(a3), "r"(b0), "r"(b1));
}

// ---------------------------------------------------------------- histinit: hist + pack B frags + up-proj
__global__ __launch_bounds__(256) void histinit_kernel(
    const int* __restrict__ receivers,
    const float* __restrict__ nf, const float* __restrict__ wup,
    const float* __restrict__ w1, const float* __restrict__ w2,
    const float* __restrict__ w3, const float* __restrict__ w4,
    const float* __restrict__ wd0, const float* __restrict__ wd1,
    const float* __restrict__ wd2)
{
    if (blockIdx.x < 1250) {
        int e = blockIdx.x * 256 + threadIdx.x;
        atomicAdd(&g_cnt[receivers[e]], 1);
        return;
    }
    if (blockIdx.x < 1514) {
        if (threadIdx.x < 32) {
            const int tile = blockIdx.x - 1250;
            const int lane = threadIdx.x;
            const int g = lane >> 2, tig = lane & 3;
            const float* W; int K, Nc, kt, nt; float sc;
            if (tile < 8)        { W = w1;  K = 8;  Nc = 64;  kt = 0;      nt = tile;    sc = 0.35355339059f; }
            else if (tile < 40)  { int t = tile-8;   W = w2;  K = 64; Nc = 64;  kt = t >> 3; nt = t & 7;  sc = 0.125f; }
            else if (tile < 72)  { int t = tile-40;  W = w3;  K = 64; Nc = 64;  kt = t >> 3; nt = t & 7;  sc = 0.125f; }
            else if (tile < 168) { int t = tile-72;  W = w4;  K = 64; Nc = 192; kt = t / 24; nt = t % 24; sc = 0.001953125f; }
            else if (tile < 200) { int t = tile-168; W = wd0; K = 64; Nc = 64;  kt = t >> 3; nt = t & 7;  sc = 0.0625f; }
            else if (tile < 232) { int t = tile-200; W = wd1; K = 64; Nc = 64;  kt = t >> 3; nt = t & 7;  sc = 0.0625f; }
            else                 { int t = tile-232; W = wd2; K = 64; Nc = 64;  kt = t >> 3; nt = t & 7;  sc = 0.0625f; }
            const int n = nt*8 + g;
            const int k0 = kt*16 + 2*tig;
            float x00 = (k0   < K) ? W[(k0  )*Nc + n]*sc : 0.f;
            float x01 = (k0+1 < K) ? W[(k0+1)*Nc + n]*sc : 0.f;
            float x10 = (k0+8 < K) ? W[(k0+8)*Nc + n]*sc : 0.f;
            float x11 = (k0+9 < K) ? W[(k0+9)*Nc + n]*sc : 0.f;
            uint32_t l0, l1;
            uint32_t h0 = split_pair(x00, x01, l0);
            uint32_t h1 = split_pair(x10, x11, l1);
            g_wfrag[tile*32 + lane] = make_uint4(h0, h1, l0, l1);
        }
        return;
    }
    // ---- up projection ----
    __shared__ float ws[CC*CC];
    __shared__ float rows[4*CC];
    const int ub = blockIdx.x - 1514;
    for (int i = threadIdx.x; i < CC*CC; i += 256) ws[i] = wup[i];
    int base = ub * 4 * CC;
    rows[threadIdx.x] = nf[base + threadIdx.x];
    __syncthreads();
    int r = threadIdx.x >> 6;
    int c = threadIdx.x & 63;
    float acc = 0.f;
    #pragma unroll
    for (int i = 0; i < CC; i++) acc = fmaf(rows[r*CC + i], ws[i*CC + c], acc);
    g_h[base + threadIdx.x] = acc * 0.125f;
}

// ---------------------------------------------------------------- scan (also re-zeroes g_cnt for next replay)
__global__ void scan_kernel() {
    __shared__ int part[1024];
    const int t = threadIdx.x;
    const int base = t * 20;
    int sum = 0;
    if (t < 1000) {
        #pragma unroll
        for (int k = 0; k < 20; k++) sum += g_cnt[base + k];
    }
    part[t] = sum;
    __syncthreads();
    #pragma unroll
    for (int off = 1; off < 1024; off <<= 1) {
        int v = (t >= off) ? part[t - off] : 0;
        __syncthreads();
        part[t] += v;
        __syncthreads();
    }
    if (t < 1000) {
        int run = part[t] - sum;
        #pragma unroll
        for (int k = 0; k < 20; k++) {
            g_off[base + k] = run;
            g_cur[base + k] = run;
            run += g_cnt[base + k];
            g_cnt[base + k] = 0;   // re-zero for next graph replay
        }
    }
    if (t == 0) g_off[NN] = NE;
}

__global__ void order_kernel(const int* __restrict__ receivers) {
    int e = blockIdx.x * blockDim.x + threadIdx.x;
    if (e < NE) {
        int pos = atomicAdd(&g_cur[receivers[e]], 1);
        g_order[pos] = e;
    }
}

// ---------------------------------------------------------------- shared mma helpers
__device__ __forceinline__ void layerK64(int tbase, int lane, float C[8][4],
                                         const uint32_t Ah[4][4], const uint32_t Al[4][4])
{
    #pragma unroll
    for (int nt = 0; nt < 8; nt++) {
        C[nt][0] = C[nt][1] = C[nt][2] = C[nt][3] = 0.f;
        #pragma unroll
        for (int kt = 0; kt < 4; kt++) {
            uint4 wf = g_wfrag[(tbase + kt*8 + nt)*32 + lane];
            mma16816(C[nt], Ah[kt][0], Ah[kt][1], Ah[kt][2], Ah[kt][3], wf.x, wf.y);
            mma16816(C[nt], Ah[kt][0], Ah[kt][1], Ah[kt][2], Ah[kt][3], wf.z, wf.w);
            mma16816(C[nt], Al[kt][0], Al[kt][1], Al[kt][2], Al[kt][3], wf.x, wf.y);
        }
    }
}

__device__ __forceinline__ void transition(const float C[8][4], uint32_t Ah[4][4], uint32_t Al[4][4])
{
    #pragma unroll
    for (int kt = 0; kt < 4; kt++) {
        const float* ca = C[2*kt];
        const float* cb = C[2*kt+1];
        Ah[kt][0] = split_pair(silu(ca[0]), silu(ca[1]), Al[kt][0]);
        Ah[kt][1] = split_pair(silu(ca[2]), silu(ca[3]), Al[kt][1]);
        Ah[kt][2] = split_pair(silu(cb[0]), silu(cb[1]), Al[kt][2]);
        Ah[kt][3] = split_pair(silu(cb[2]), silu(cb[3]), Al[kt][3]);
    }
}

// tile row stride (floats) — round-10 single-pass layout
#define TROW 194
#define TILE_F (16*TROW)
#define EY_OFF (4*TILE_F)
#define ESMEM_F (4*TILE_F + 4*128 + 4*16)

// ---------------------------------------------------------------- edgeM: MLP (mma) + fused segmented scatter (round-10)
__global__ __launch_bounds__(128) void edgeM_kernel(
    const float* __restrict__ vectors, const float* __restrict__ radial,
    const int* __restrict__ senders, const int* __restrict__ receivers)
{
    extern __shared__ float esm[];
    const int wid = threadIdx.x >> 5;
    const int lane = threadIdx.x & 31;
    float* tw = esm + wid*TILE_F;
    float* yw = esm + EY_OFF + wid*128;
    int*   rcw = (int*)(esm + EY_OFF + 4*128) + wid*16;

    const int wt = blockIdx.x*4 + wid;
    const int g = lane >> 2, tig = lane & 3;
    const int base = wt*16;
    const int p0 = base + g, p1 = p0 + 8;
    const int e0 = g_order[p0], e1 = g_order[p1];

    uint32_t Ah[4][4], Al[4][4];
    {
        float2 r0 = *(const float2*)(radial + (size_t)e0*8 + 2*tig);
        float2 r1 = *(const float2*)(radial + (size_t)e1*8 + 2*tig);
        Ah[0][0] = split_pair(r0.x, r0.y, Al[0][0]);
        Ah[0][1] = split_pair(r1.x, r1.y, Al[0][1]);
        Ah[0][2] = 0; Ah[0][3] = 0; Al[0][2] = 0; Al[0][3] = 0;
    }

    float C[8][4];
    // ---- L1 ----
    #pragma unroll
    for (int nt = 0; nt < 8; nt++) {
        C[nt][0] = C[nt][1] = C[nt][2] = C[nt][3] = 0.f;
        uint4 wf = g_wfrag[nt*32 + lane];
        mma16816(C[nt], Ah[0][0], Ah[0][1], Ah[0][2], Ah[0][3], wf.x, wf.y);
        mma16816(C[nt], Ah[0][0], Ah[0][1], Ah[0][2], Ah[0][3], wf.z, wf.w);
        mma16816(C[nt], Al[0][0], Al[0][1], Al[0][2], Al[0][3], wf.x, wf.y);
    }
    transition(C, Ah, Al);
    layerK64(8, lane, C, Ah, Al);    // L2
    transition(C, Ah, Al);
    layerK64(40, lane, C, Ah, Al);   // L3
    transition(C, Ah, Al);

    // ---- L4 (N=192) -> smem tile ----
    const int snd0 = senders[e0], snd1 = senders[e1];
    const float* h0r = g_h + (size_t)snd0*64;
    const float* h1r = g_h + (size_t)snd1*64;

    #pragma unroll
    for (int p = 0; p < 3; p++) {
        float D[8][4];
        #pragma unroll
        for (int ntl = 0; ntl < 8; ntl++) {
            D[ntl][0] = D[ntl][1] = D[ntl][2] = D[ntl][3] = 0.f;
            #pragma unroll
            for (int kt = 0; kt < 4; kt++) {
                uint4 wf = g_wfrag[(72 + kt*24 + p*8 + ntl)*32 + lane];
                mma16816(D[ntl], Ah[kt][0], Ah[kt][1], Ah[kt][2], Ah[kt][3], wf.x, wf.y);
                mma16816(D[ntl], Ah[kt][0], Ah[kt][1], Ah[kt][2], Ah[kt][3], wf.z, wf.w);
                mma16816(D[ntl], Al[kt][0], Al[kt][1], Al[kt][2], Al[kt][3], wf.x, wf.y);
            }
        }
        #pragma unroll
        for (int ntl = 0; ntl < 8; ntl++) {
            int col = 8*ntl + 2*tig;
            float2 h0 = *(const float2*)(h0r + col);
            float2 h1 = *(const float2*)(h1r + col);
            *(float2*)(tw + g*TROW + p*64 + col)     = make_float2(D[ntl][0]*h0.x, D[ntl][1]*h0.y);
            *(float2*)(tw + (g+8)*TROW + p*64 + col) = make_float2(D[ntl][2]*h1.x, D[ntl][3]*h1.y);
        }
    }

    // ---- SH + receiver ids -> smem ----
    if (lane < 16) {
        const int e = g_order[base + lane];
        float vx = vectors[e*3], vy = vectors[e*3+1], vz = vectors[e*3+2];
        float inv = rsqrtf(vx*vx + vy*vy + vz*vz);
        float ux = vx*inv, uy = vy*inv, uz = vz*inv;
        const float SQ3 = 1.7320508075688772f, S15 = 3.872983346207417f;
        const float HS5 = 1.118033988749895f;
        float* yr = yw + lane*8;
        yr[0] = SQ3*ux; yr[1] = SQ3*uy; yr[2] = SQ3*uz;
        yr[3] = S15*ux*uy; yr[4] = S15*uy*uz; yr[5] = HS5*(3.f*uz*uz - 1.f);
        yr[6] = S15*ux*uz; yr[7] = 0.5f*S15*(ux*ux - uy*uy);
        rcw[lane] = receivers[e];
    }
    __syncwarp();

    // ---- fused segmented reduction ----
    const int c0 = 2*lane;
    float acc[9][2];
    #pragma unroll
    for (int m = 0; m < 9; m++) { acc[m][0] = 0.f; acc[m][1] = 0.f; }
    int prev = rcw[0];

    #pragma unroll 1
    for (int r = 0; r < 16; r++) {
        int rc = rcw[r];
        if (rc != prev) {
            float* ab = g_agg + (size_t)prev*64 + c0;
            #pragma unroll
            for (int m = 0; m < 9; m++) {
                red2(ab + (size_t)m*PL, acc[m][0], acc[m][1]);
                acc[m][0] = 0.f; acc[m][1] = 0.f;
            }
            prev = rc;
        }
        const float* tr = tw + r*TROW;
        float2 t0 = *(const float2*)(tr + c0);
        float2 t1 = *(const float2*)(tr + 64 + c0);
        float2 t2 = *(const float2*)(tr + 128 + c0);
        const float* yr = yw + r*8;
        acc[0][0] += t0.x; acc[0][1] += t0.y;
        #pragma unroll
        for (int m = 0; m < 3; m++) {
            float ym = yr[m];
            acc[1+m][0] = fmaf(t1.x, ym, acc[1+m][0]);
            acc[1+m][1] = fmaf(t1.y, ym, acc[1+m][1]);
        }
        #pragma unroll
        for (int m = 0; m < 5; m++) {
            float ym = yr[3+m];
            acc[4+m][0] = fmaf(t2.x, ym, acc[4+m][0]);
            acc[4+m][1] = fmaf(t2.y, ym, acc[4+m][1]);
        }
    }
    {
        float* ab = g_agg + (size_t)prev*64 + c0;
        #pragma unroll
        for (int m = 0; m < 9; m++)
            red2(ab + (size_t)m*PL, acc[m][0], acc[m][1]);
    }
}

// ---------------------------------------------------------------- down projection via mma, smem-staged A
#define NJOBS (9*1250)
#define DTROW 68
__global__ __launch_bounds__(128) void downM_kernel(float* __restrict__ out)
{
    __shared__ float dtile[4][16*DTROW];
    const int wid = threadIdx.x >> 5;
    const int job = blockIdx.x*4 + wid;
    if (job >= NJOBS) return;
    const int lane = threadIdx.x & 31;
    const int g = lane >> 2, tig = lane & 3;
    const int plane = job / 1250;
    const int n0 = (job - plane*1250) * 16;

    float* tile = dtile[wid];
    {   // coalesced stage of agg[plane][n0..n0+16][0..64]
        const float4* src = (const float4*)(g_agg + (size_t)plane*PL + (size_t)n0*64);
        #pragma unroll
        for (int j = 0; j < 8; j++) {
            int idx = j*32 + lane;          // 0..255 float4s = 16 rows x 16 float4
            float4 v = src[idx];
            float* tp = tile + (idx >> 4)*DTROW + (idx & 15)*4;
            tp[0] = v.x; tp[1] = v.y; tp[2] = v.z; tp[3] = v.w;
        }
    }
    __syncwarp();

    uint32_t Ah[4][4], Al[4][4];
    #pragma unroll
    for (int kt = 0; kt < 4; kt++) {
        const int c0 = kt*16 + 2*tig;
        const float* r0p = tile + g*DTROW + c0;
        const float* r1p = tile + (g+8)*DTROW + c0;
        float2 a00 = *(const float2*)(r0p);
        float2 a01 = *(const float2*)(r0p + 8);
        float2 a10 = *(const float2*)(r1p);
        float2 a11 = *(const float2*)(r1p + 8);
        Ah[kt][0] = split_pair(a00.x, a00.y, Al[kt][0]);
        Ah[kt][1] = split_pair(a10.x, a10.y, Al[kt][1]);
        Ah[kt][2] = split_pair(a01.x, a01.y, Al[kt][2]);
        Ah[kt][3] = split_pair(a11.x, a11.y, Al[kt][3]);
    }

    const int tbase = 168 + (plane == 0 ? 0 : (plane < 4 ? 32 : 64));
    float C[8][4];
    layerK64(tbase, lane, C, Ah, Al);

    float* ob0 = out + (size_t)(n0+g)*576;
    float* ob1 = out + (size_t)(n0+g+8)*576;
    if (plane == 0) {
        #pragma unroll
        for (int nt = 0; nt < 8; nt++) {
            int d = 8*nt + 2*tig;
            *(float2*)(ob0 + d) = make_float2(C[nt][0], C[nt][1]);
            *(float2*)(ob1 + d) = make_float2(C[nt][2], C[nt][3]);
        }
    } else if (plane < 4) {
        float* b0 = ob0 + 64 + (plane - 1);
        float* b1 = ob1 + 64 + (plane - 1);
        #pragma unroll
        for (int nt = 0; nt < 8; nt++) {
            int d = 8*nt + 2*tig;
            b0[3*d] = C[nt][0]; b0[3*(d+1)] = C[nt][1];
            b1[3*d] = C[nt][2]; b1[3*(d+1)] = C[nt][3];
        }
    } else {
        float* b0 = ob0 + 256 + (plane - 4);
        float* b1 = ob1 + 256 + (plane - 4);
        #pragma unroll
        for (int nt = 0; nt < 8; nt++) {
            int d = 8*nt + 2*tig;
            b0[5*d] = C[nt][0]; b0[5*(d+1)] = C[nt][1];
            b1[5*d] = C[nt][2]; b1[5*(d+1)] = C[nt][3];
        }
    }
}

// ---------------------------------------------------------------- launch
extern "C" void kernel_launch(void* const* d_in, const int* in_sizes, int n_in,
                              void* d_out, int out_size)
{
    const float* vectors    = (const float*)d_in[0];
    const float* node_feats = (const float*)d_in[1];
    const float* radial     = (const float*)d_in[2];
    const int*   senders    = (const int*)  d_in[3];
    const int*   receivers  = (const int*)  d_in[4];
    const float* w_up       = (const float*)d_in[5];
    const float* mlp_w1     = (const float*)d_in[6];
    const float* mlp_w2     = (const float*)d_in[7];
    const float* mlp_w3     = (const float*)d_in[8];
    const float* mlp_w4     = (const float*)d_in[9];
    const float* w_down0    = (const float*)d_in[10];
    const float* w_down1    = (const float*)d_in[11];
    const float* w_down2    = (const float*)d_in[12];
    float* out = (float*)d_out;

    const int E_SMEM = ESMEM_F * 4;   // 51968 B
    cudaFuncSetAttribute(edgeM_kernel, cudaFuncAttributeMaxDynamicSharedMemorySize, E_SMEM);

    void* aggp = nullptr;
    cudaGetSymbolAddress(&aggp, g_agg);
    cudaMemsetAsync(aggp, 0, (size_t)9 * PL * sizeof(float));                     // launch 1

    histinit_kernel<<<1514 + NN/4, 256>>>(receivers, node_feats, w_up,            // launch 2
                                          mlp_w1, mlp_w2, mlp_w3, mlp_w4,
                                          w_down0, w_down1, w_down2);
    scan_kernel<<<1, 1024>>>();                                                   // launch 3
    order_kernel<<<(NE + 255)/256, 256>>>(receivers);                             // launch 4
    edgeM_kernel<<<NE/(16*4), 128, E_SMEM>>>(vectors, radial, senders, receivers);// launch 5  <- ncu slot
    downM_kernel<<<(NJOBS + 3)/4, 128>>>(out);                                    // launch 6
}

// round 14
// speedup vs baseline: 1.1003x; 1.0375x over previous
#include <cuda_runtime.h>
#include <cuda_bf16.h>
#include <cstdint>

#define NN 20000
#define NE 320000
#define CC 64
#define PL (NN*CC)

typedef unsigned long long ull;

// Scratch (allocation-free rule: __device__ globals)
__device__ __align__(16) float g_h[NN*CC];        // 5.1 MB
__device__ __align__(16) float g_agg[9*PL];       // 46 MB (atomic target, planar)
__device__ __align__(16) uint4 g_wfrag[264*32];   // 135 KB packed B fragments (MLP + down)
__device__ int g_cnt[NN];
__device__ int g_off[NN+1];
__device__ int g_cur[NN];
__device__ int g_order[NE];

// silu via hardware tanh: x*sigmoid(x) = 0.5x*tanh(0.5x) + 0.5x
__device__ __forceinline__ float silu(float x) {
    float hx = 0.5f * x;
    float t;
    asm("tanh.approx.f32 %0, %1;" : "=f"(t) : "f"(hx));
    return fmaf(hx, t, hx);
}
__device__ __forceinline__ void red2(float* p, float a, float b) {
    asm volatile("red.global.add.v2.f32 [%0], {%1,%2};" :: "l"(p), "f"(a), "f"(b) : "memory");
}

// pack (x0 -> low half, x1 -> high half) as bf16x2; return hi-word, write lo(residual)-word
__device__ __forceinline__ uint32_t split_pair(float x0, float x1, uint32_t& lw) {
    uint32_t hw;
    asm("cvt.rn.bf16x2.f32 %0, %1, %2;" : "=r"(hw) : "f"(x1), "f"(x0));
    float h0 = __uint_as_float(hw << 16);
    float h1 = __uint_as_float(hw & 0xffff0000u);
    asm("cvt.rn.bf16x2.f32 %0, %1, %2;" : "=r"(lw) : "f"(x1 - h1), "f"(x0 - h0));
    return hw;
}

__device__ __forceinline__ void mma16816(float c[4],
    uint32_t a0, uint32_t a1, uint32_t a2, uint32_t a3, uint32_t b0, uint32_t b1)
{
    asm volatile("mma.sync.aligned.m16n8k16.row.col.f32.bf16.bf16.f32 "
        "{%0,%1,%2,%3},{%4,%5,%6,%7},{%8,%9},{%0,%1,%2,%3};"
        : "+f"(c[0]), "+f"(c[1]), "+f"(c[2]), "+f"(c[3])
        : "r"(a0), "r"(a1), "r"(a2), "r"(a3), "r"(b0), "r"(b1));
}

// ---------------------------------------------------------------- histinit: hist + pack B frags + up-proj
__global__ __launch_bounds__(256) void histinit_kernel(
    const int* __restrict__ receivers,
    const float* __restrict__ nf, const float* __restrict__ wup,
    const float* __restrict__ w1, const float* __restrict__ w2,
    const float* __restrict__ w3, const float* __restrict__ w4,
    const float* __restrict__ wd0, const float* __restrict__ wd1,
    const float* __restrict__ wd2)
{
    if (blockIdx.x < 1250) {
        int e = blockIdx.x * 256 + threadIdx.x;
        atomicAdd(&g_cnt[receivers[e]], 1);
        return;
    }
    if (blockIdx.x < 1514) {
        if (threadIdx.x < 32) {
            const int tile = blockIdx.x - 1250;
            const int lane = threadIdx.x;
            const int g = lane >> 2, tig = lane & 3;
            const float* W; int K, Nc, kt, nt; float sc;
            if (tile < 8)        { W = w1;  K = 8;  Nc = 64;  kt = 0;      nt = tile;    sc = 0.35355339059f; }
            else if (tile < 40)  { int t = tile-8;   W = w2;  K = 64; Nc = 64;  kt = t >> 3; nt = t & 7;  sc = 0.125f; }
            else if (tile < 72)  { int t = tile-40;  W = w3;  K = 64; Nc = 64;  kt = t >> 3; nt = t & 7;  sc = 0.125f; }
            else if (tile < 168) { int t = tile-72;  W = w4;  K = 64; Nc = 192; kt = t / 24; nt = t % 24; sc = 0.001953125f; }
            else if (tile < 200) { int t = tile-168; W = wd0; K = 64; Nc = 64;  kt = t >> 3; nt = t & 7;  sc = 0.0625f; }
            else if (tile < 232) { int t = tile-200; W = wd1; K = 64; Nc = 64;  kt = t >> 3; nt = t & 7;  sc = 0.0625f; }
            else                 { int t = tile-232; W = wd2; K = 64; Nc = 64;  kt = t >> 3; nt = t & 7;  sc = 0.0625f; }
            const int n = nt*8 + g;
            const int k0 = kt*16 + 2*tig;
            float x00 = (k0   < K) ? W[(k0  )*Nc + n]*sc : 0.f;
            float x01 = (k0+1 < K) ? W[(k0+1)*Nc + n]*sc : 0.f;
            float x10 = (k0+8 < K) ? W[(k0+8)*Nc + n]*sc : 0.f;
            float x11 = (k0+9 < K) ? W[(k0+9)*Nc + n]*sc : 0.f;
            uint32_t l0, l1;
            uint32_t h0 = split_pair(x00, x01, l0);
            uint32_t h1 = split_pair(x10, x11, l1);
            g_wfrag[tile*32 + lane] = make_uint4(h0, h1, l0, l1);
        }
        return;
    }
    // ---- up projection ----
    __shared__ float ws[CC*CC];
    __shared__ float rows[4*CC];
    const int ub = blockIdx.x - 1514;
    for (int i = threadIdx.x; i < CC*CC; i += 256) ws[i] = wup[i];
    int base = ub * 4 * CC;
    rows[threadIdx.x] = nf[base + threadIdx.x];
    __syncthreads();
    int r = threadIdx.x >> 6;
    int c = threadIdx.x & 63;
    float acc = 0.f;
    #pragma unroll
    for (int i = 0; i < CC; i++) acc = fmaf(rows[r*CC + i], ws[i*CC + c], acc);
    g_h[base + threadIdx.x] = acc * 0.125f;
}

// ---------------------------------------------------------------- scan (also re-zeroes g_cnt for next replay)
__global__ void scan_kernel() {
    __shared__ int part[1024];
    const int t = threadIdx.x;
    const int base = t * 20;
    int sum = 0;
    if (t < 1000) {
        #pragma unroll
        for (int k = 0; k < 20; k++) sum += g_cnt[base + k];
    }
    part[t] = sum;
    __syncthreads();
    #pragma unroll
    for (int off = 1; off < 1024; off <<= 1) {
        int v = (t >= off) ? part[t - off] : 0;
        __syncthreads();
        part[t] += v;
        __syncthreads();
    }
    if (t < 1000) {
        int run = part[t] - sum;
        #pragma unroll
        for (int k = 0; k < 20; k++) {
            g_off[base + k] = run;
            g_cur[base + k] = run;
            run += g_cnt[base + k];
            g_cnt[base + k] = 0;   // re-zero for next graph replay
        }
    }
    if (t == 0) g_off[NN] = NE;
}

__global__ void order_kernel(const int* __restrict__ receivers) {
    int e = blockIdx.x * blockDim.x + threadIdx.x;
    if (e < NE) {
        int pos = atomicAdd(&g_cur[receivers[e]], 1);
        g_order[pos] = e;
    }
}

// ---------------------------------------------------------------- shared mma helpers
__device__ __forceinline__ void layerK64(int tbase, int lane, float C[8][4],
                                         const uint32_t Ah[4][4], const uint32_t Al[4][4])
{
    #pragma unroll
    for (int nt = 0; nt < 8; nt++) {
        C[nt][0] = C[nt][1] = C[nt][2] = C[nt][3] = 0.f;
        #pragma unroll
        for (int kt = 0; kt < 4; kt++) {
            uint4 wf = g_wfrag[(tbase + kt*8 + nt)*32 + lane];
            mma16816(C[nt], Ah[kt][0], Ah[kt][1], Ah[kt][2], Ah[kt][3], wf.x, wf.y);
            mma16816(C[nt], Ah[kt][0], Ah[kt][1], Ah[kt][2], Ah[kt][3], wf.z, wf.w);
            mma16816(C[nt], Al[kt][0], Al[kt][1], Al[kt][2], Al[kt][3], wf.x, wf.y);
        }
    }
}

__device__ __forceinline__ void transition(const float C[8][4], uint32_t Ah[4][4], uint32_t Al[4][4])
{
    #pragma unroll
    for (int kt = 0; kt < 4; kt++) {
        const float* ca = C[2*kt];
        const float* cb = C[2*kt+1];
        Ah[kt][0] = split_pair(silu(ca[0]), silu(ca[1]), Al[kt][0]);
        Ah[kt][1] = split_pair(silu(ca[2]), silu(ca[3]), Al[kt][1]);
        Ah[kt][2] = split_pair(silu(cb[0]), silu(cb[1]), Al[kt][2]);
        Ah[kt][3] = split_pair(silu(cb[2]), silu(cb[3]), Al[kt][3]);
    }
}

// tile row stride (floats) — round-10 single-pass layout
#define TROW 194
#define TILE_F (16*TROW)
#define EY_OFF (4*TILE_F)
#define ESMEM_F (4*TILE_F + 4*128 + 4*16)

// ---------------------------------------------------------------- edgeM: MLP (mma) + fused segmented scatter
// __launch_bounds__(128, 4): cap regs at 128 so 4 blocks/SM fit (was 142 regs -> 3 blocks, occ 18%)
__global__ __launch_bounds__(128, 4) void edgeM_kernel(
    const float* __restrict__ vectors, const float* __restrict__ radial,
    const int* __restrict__ senders, const int* __restrict__ receivers)
{
    extern __shared__ float esm[];
    const int wid = threadIdx.x >> 5;
    const int lane = threadIdx.x & 31;
    float* tw = esm + wid*TILE_F;
    float* yw = esm + EY_OFF + wid*128;
    int*   rcw = (int*)(esm + EY_OFF + 4*128) + wid*16;

    const int wt = blockIdx.x*4 + wid;
    const int g = lane >> 2, tig = lane & 3;
    const int base = wt*16;
    const int p0 = base + g, p1 = p0 + 8;
    const int e0 = g_order[p0], e1 = g_order[p1];

    uint32_t Ah[4][4], Al[4][4];
    {
        float2 r0 = *(const float2*)(radial + (size_t)e0*8 + 2*tig);
        float2 r1 = *(const float2*)(radial + (size_t)e1*8 + 2*tig);
        Ah[0][0] = split_pair(r0.x, r0.y, Al[0][0]);
        Ah[0][1] = split_pair(r1.x, r1.y, Al[0][1]);
        Ah[0][2] = 0; Ah[0][3] = 0; Al[0][2] = 0; Al[0][3] = 0;
    }

    float C[8][4];
    // ---- L1 ----
    #pragma unroll
    for (int nt = 0; nt < 8; nt++) {
        C[nt][0] = C[nt][1] = C[nt][2] = C[nt][3] = 0.f;
        uint4 wf = g_wfrag[nt*32 + lane];
        mma16816(C[nt], Ah[0][0], Ah[0][1], Ah[0][2], Ah[0][3], wf.x, wf.y);
        mma16816(C[nt], Ah[0][0], Ah[0][1], Ah[0][2], Ah[0][3], wf.z, wf.w);
        mma16816(C[nt], Al[0][0], Al[0][1], Al[0][2], Al[0][3], wf.x, wf.y);
    }
    transition(C, Ah, Al);
    layerK64(8, lane, C, Ah, Al);    // L2
    transition(C, Ah, Al);
    layerK64(40, lane, C, Ah, Al);   // L3
    transition(C, Ah, Al);

    // ---- L4 (N=192) -> smem tile ----
    const int snd0 = senders[e0], snd1 = senders[e1];
    const float* h0r = g_h + (size_t)snd0*64;
    const float* h1r = g_h + (size_t)snd1*64;

    #pragma unroll
    for (int p = 0; p < 3; p++) {
        float D[8][4];
        #pragma unroll
        for (int ntl = 0; ntl < 8; ntl++) {
            D[ntl][0] = D[ntl][1] = D[ntl][2] = D[ntl][3] = 0.f;
            #pragma unroll
            for (int kt = 0; kt < 4; kt++) {
                uint4 wf = g_wfrag[(72 + kt*24 + p*8 + ntl)*32 + lane];
                mma16816(D[ntl], Ah[kt][0], Ah[kt][1], Ah[kt][2], Ah[kt][3], wf.x, wf.y);
                mma16816(D[ntl], Ah[kt][0], Ah[kt][1], Ah[kt][2], Ah[kt][3], wf.z, wf.w);
                mma16816(D[ntl], Al[kt][0], Al[kt][1], Al[kt][2], Al[kt][3], wf.x, wf.y);
            }
        }
        #pragma unroll
        for (int ntl = 0; ntl < 8; ntl++) {
            int col = 8*ntl + 2*tig;
            float2 h0 = *(const float2*)(h0r + col);
            float2 h1 = *(const float2*)(h1r + col);
            *(float2*)(tw + g*TROW + p*64 + col)     = make_float2(D[ntl][0]*h0.x, D[ntl][1]*h0.y);
            *(float2*)(tw + (g+8)*TROW + p*64 + col) = make_float2(D[ntl][2]*h1.x, D[ntl][3]*h1.y);
        }
    }

    // ---- SH + receiver ids -> smem ----
    if (lane < 16) {
        const int e = g_order[base + lane];
        float vx = vectors[e*3], vy = vectors[e*3+1], vz = vectors[e*3+2];
        float inv = rsqrtf(vx*vx + vy*vy + vz*vz);
        float ux = vx*inv, uy = vy*inv, uz = vz*inv;
        const float SQ3 = 1.7320508075688772f, S15 = 3.872983346207417f;
        const float HS5 = 1.118033988749895f;
        float* yr = yw + lane*8;
        yr[0] = SQ3*ux; yr[1] = SQ3*uy; yr[2] = SQ3*uz;
        yr[3] = S15*ux*uy; yr[4] = S15*uy*uz; yr[5] = HS5*(3.f*uz*uz - 1.f);
        yr[6] = S15*ux*uz; yr[7] = 0.5f*S15*(ux*ux - uy*uy);
        rcw[lane] = receivers[e];
    }
    __syncwarp();

    // ---- fused segmented reduction ----
    const int c0 = 2*lane;
    float acc[9][2];
    #pragma unroll
    for (int m = 0; m < 9; m++) { acc[m][0] = 0.f; acc[m][1] = 0.f; }
    int prev = rcw[0];

    #pragma unroll 1
    for (int r = 0; r < 16; r++) {
        int rc = rcw[r];
        if (rc != prev) {
            float* ab = g_agg + (size_t)prev*64 + c0;
            #pragma unroll
            for (int m = 0; m < 9; m++) {
                red2(ab + (size_t)m*PL, acc[m][0], acc[m][1]);
                acc[m][0] = 0.f; acc[m][1] = 0.f;
            }
            prev = rc;
        }
        const float* tr = tw + r*TROW;
        float2 t0 = *(const float2*)(tr + c0);
        float2 t1 = *(const float2*)(tr + 64 + c0);
        float2 t2 = *(const float2*)(tr + 128 + c0);
        const float* yr = yw + r*8;
        acc[0][0] += t0.x; acc[0][1] += t0.y;
        #pragma unroll
        for (int m = 0; m < 3; m++) {
            float ym = yr[m];
            acc[1+m][0] = fmaf(t1.x, ym, acc[1+m][0]);
            acc[1+m][1] = fmaf(t1.y, ym, acc[1+m][1]);
        }
        #pragma unroll
        for (int m = 0; m < 5; m++) {
            float ym = yr[3+m];
            acc[4+m][0] = fmaf(t2.x, ym, acc[4+m][0]);
            acc[4+m][1] = fmaf(t2.y, ym, acc[4+m][1]);
        }
    }
    {
        float* ab = g_agg + (size_t)prev*64 + c0;
        #pragma unroll
        for (int m = 0; m < 9; m++)
            red2(ab + (size_t)m*PL, acc[m][0], acc[m][1]);
    }
}

// ---------------------------------------------------------------- down projection via mma (round-10 direct loads)
#define NJOBS (9*1250)
__global__ __launch_bounds__(128) void downM_kernel(float* __restrict__ out)
{
    const int job = blockIdx.x*4 + (threadIdx.x >> 5);
    if (job >= NJOBS) return;
    const int lane = threadIdx.x & 31;
    const int g = lane >> 2, tig = lane & 3;
    const int plane = job / 1250;
    const int n0 = (job - plane*1250) * 16;

    const float* ar = g_agg + (size_t)plane*PL;
    uint32_t Ah[4][4], Al[4][4];
    #pragma unroll
    for (int kt = 0; kt < 4; kt++) {
        const int c0 = kt*16 + 2*tig;
        const float* r0p = ar + (size_t)(n0+g)*64 + c0;
        const float* r1p = ar + (size_t)(n0+g+8)*64 + c0;
        float2 a00 = *(const float2*)(r0p);
        float2 a01 = *(const float2*)(r0p + 8);
        float2 a10 = *(const float2*)(r1p);
        float2 a11 = *(const float2*)(r1p + 8);
        Ah[kt][0] = split_pair(a00.x, a00.y, Al[kt][0]);
        Ah[kt][1] = split_pair(a10.x, a10.y, Al[kt][1]);
        Ah[kt][2] = split_pair(a01.x, a01.y, Al[kt][2]);
        Ah[kt][3] = split_pair(a11.x, a11.y, Al[kt][3]);
    }

    const int tbase = 168 + (plane == 0 ? 0 : (plane < 4 ? 32 : 64));
    float C[8][4];
    layerK64(tbase, lane, C, Ah, Al);

    float* ob0 = out + (size_t)(n0+g)*576;
    float* ob1 = out + (size_t)(n0+g+8)*576;
    if (plane == 0) {
        #pragma unroll
        for (int nt = 0; nt < 8; nt++) {
            int d = 8*nt + 2*tig;
            *(float2*)(ob0 + d) = make_float2(C[nt][0], C[nt][1]);
            *(float2*)(ob1 + d) = make_float2(C[nt][2], C[nt][3]);
        }
    } else if (plane < 4) {
        float* b0 = ob0 + 64 + (plane - 1);
        float* b1 = ob1 + 64 + (plane - 1);
        #pragma unroll
        for (int nt = 0; nt < 8; nt++) {
            int d = 8*nt + 2*tig;
            b0[3*d] = C[nt][0]; b0[3*(d+1)] = C[nt][1];
            b1[3*d] = C[nt][2]; b1[3*(d+1)] = C[nt][3];
        }
    } else {
        float* b0 = ob0 + 256 + (plane - 4);
        float* b1 = ob1 + 256 + (plane - 4);
        #pragma unroll
        for (int nt = 0; nt < 8; nt++) {
            int d = 8*nt + 2*tig;
            b0[5*d] = C[nt][0]; b0[5*(d+1)] = C[nt][1];
            b1[5*d] = C[nt][2]; b1[5*(d+1)] = C[nt][3];
        }
    }
}

// ---------------------------------------------------------------- launch
extern "C" void kernel_launch(void* const* d_in, const int* in_sizes, int n_in,
                              void* d_out, int out_size)
{
    const float* vectors    = (const float*)d_in[0];
    const float* node_feats = (const float*)d_in[1];
    const float* radial     = (const float*)d_in[2];
    const int*   senders    = (const int*)  d_in[3];
    const int*   receivers  = (const int*)  d_in[4];
    const float* w_up       = (const float*)d_in[5];
    const float* mlp_w1     = (const float*)d_in[6];
    const float* mlp_w2     = (const float*)d_in[7];
    const float* mlp_w3     = (const float*)d_in[8];
    const float* mlp_w4     = (const float*)d_in[9];
    const float* w_down0    = (const float*)d_in[10];
    const float* w_down1    = (const float*)d_in[11];
    const float* w_down2    = (const float*)d_in[12];
    float* out = (float*)d_out;

    const int E_SMEM = ESMEM_F * 4;   // 51968 B; 4 blocks/SM = 208KB <= 228KB carveout
    cudaFuncSetAttribute(edgeM_kernel, cudaFuncAttributeMaxDynamicSharedMemorySize, E_SMEM);

    void* aggp = nullptr;
    cudaGetSymbolAddress(&aggp, g_agg);
    cudaMemsetAsync(aggp, 0, (size_t)9 * PL * sizeof(float));                     // launch 1

    histinit_kernel<<<1514 + NN/4, 256>>>(receivers, node_feats, w_up,            // launch 2
                                          mlp_w1, mlp_w2, mlp_w3, mlp_w4,
                                          w_down0, w_down1, w_down2);
    scan_kernel<<<1, 1024>>>();                                                   // launch 3
    order_kernel<<<(NE + 255)/256, 256>>>(receivers);                             // launch 4
    edgeM_kernel<<<NE/(16*4), 128, E_SMEM>>>(vectors, radial, senders, receivers);// launch 5  <- ncu slot
    downM_kernel<<<(NJOBS + 3)/4, 128>>>(out);                                    // launch 6
}